// round 2
// baseline (speedup 1.0000x reference)
#include <cuda_runtime.h>
#include <math.h>
#include <stdint.h>

// ---------------- constants ----------------
#define T_FR   8
#define NSEQ   197          // tokens per frame (196 patches + cls)
#define NTOK   1576         // T_FR * NSEQ
#define DMODEL 768
#define NHEAD  12
#define DHEAD  64
#define DMLP   3072
#define QKVW   2304
#define NPAT   196
#define SCALE_ 0.125f       // DHEAD^-0.5

// ---------------- scratch (single device global, partitioned on host) ----------
// patches:  1568*768  = 1204224
// emb:      1568*768  = 1204224
// h:        1576*768  = 1210368
// a:        1576*768  = 1210368
// qkv:      1576*2304 = 3631104
// scores:   12*1576*1576 = 29806512
// o:        1576*768  = 1210368
// mlp:      1576*3072 = 4841472
// vmean:    12*8*64   = 6144
#define WS_PATCH   0
#define WS_EMB     (WS_PATCH + 1204224)
#define WS_H       (WS_EMB + 1204224)
#define WS_A       (WS_H + 1210368)
#define WS_QKV     (WS_A + 1210368)
#define WS_SCORES  (WS_QKV + 3631104)
#define WS_O       (WS_SCORES + 29806512)
#define WS_MLP     (WS_O + 1210368)
#define WS_VMEAN   (WS_MLP + 4841472)
#define WS_TOTAL   (WS_VMEAN + 6144)

__device__ float g_ws[WS_TOTAL];

// ---------------- patch gather -------------------------------------------------
// P[m][k], m = t*196+p, k = c*256 + i*16 + j ; value = x[0][t][c][hp*16+i][wp*16+j]
__global__ void gather_patches(const float* __restrict__ x, float* __restrict__ P) {
    int idx = blockIdx.x * 256 + threadIdx.x;
    if (idx >= 1568 * 768) return;
    int m = idx / 768, k = idx - m * 768;
    int t = m / NPAT, p = m - t * NPAT;
    int hp = p / 14, wp = p - hp * 14;
    int c = k >> 8;
    int r = (k >> 4) & 15;
    int j = k & 15;
    P[idx] = x[(((size_t)(t * 3 + c) * 224) + hp * 16 + r) * 224 + wp * 16 + j];
}

// ---------------- token assembly (replicates the torch axis scramble) ----------
__global__ void assemble_h(const float* __restrict__ emb, const float* __restrict__ cls,
                           const float* __restrict__ pos, float* __restrict__ h) {
    int idx = blockIdx.x * 256 + threadIdx.x;
    if (idx >= NTOK * DMODEL) return;
    int s = idx / DMODEL, d = idx - s * DMODEL;
    int t = s / NSEQ, n = s - t * NSEQ;
    float v;
    if (n == 0) {
        v = cls[d];
    } else {
        int l = (n - 1) * DMODEL + d;
        int dsrc = l / NPAT;
        int psrc = l - dsrc * NPAT;
        v = emb[((size_t)t * NPAT + psrc) * DMODEL + dsrc];
    }
    h[idx] = v + pos[n * DMODEL + d];
}

// ---------------- generic C = A@B (+bias)(+res), B row-major [K,N] -------------
// BM=BN=64, BK=16, 256 threads, 4x4 per thread. N % 64 == 0, K % 16 == 0 assumed.
__global__ void sgemm_bias(const float* __restrict__ A, const float* __restrict__ B,
                           const float* __restrict__ bias, const float* __restrict__ res,
                           float* __restrict__ C, int M, int N, int K) {
    __shared__ float As[16][64];
    __shared__ float Bs[16][64];
    const int tid = threadIdx.x;
    const int tx = tid & 15, ty = tid >> 4;
    const int row0 = blockIdx.y * 64, col0 = blockIdx.x * 64;
    const int ar = tid >> 2, ac = (tid & 3) << 2;      // A: row 0..63, k 0..12
    const int br = tid >> 4, bc = (tid & 15) << 2;     // B: k 0..15, col 0..60
    float acc[4][4] = {};
    for (int k0 = 0; k0 < K; k0 += 16) {
        float4 av = make_float4(0.f, 0.f, 0.f, 0.f);
        int arow = row0 + ar;
        if (arow < M) av = *(const float4*)(A + (size_t)arow * K + k0 + ac);
        As[ac + 0][ar] = av.x; As[ac + 1][ar] = av.y;
        As[ac + 2][ar] = av.z; As[ac + 3][ar] = av.w;
        float4 bv = *(const float4*)(B + (size_t)(k0 + br) * N + col0 + bc);
        *(float4*)&Bs[br][bc] = bv;
        __syncthreads();
#pragma unroll
        for (int kk = 0; kk < 16; kk++) {
            float4 a = *(const float4*)&As[kk][ty << 2];
            float4 b = *(const float4*)&Bs[kk][tx << 2];
            acc[0][0] += a.x * b.x; acc[0][1] += a.x * b.y; acc[0][2] += a.x * b.z; acc[0][3] += a.x * b.w;
            acc[1][0] += a.y * b.x; acc[1][1] += a.y * b.y; acc[1][2] += a.y * b.z; acc[1][3] += a.y * b.w;
            acc[2][0] += a.z * b.x; acc[2][1] += a.z * b.y; acc[2][2] += a.z * b.z; acc[2][3] += a.z * b.w;
            acc[3][0] += a.w * b.x; acc[3][1] += a.w * b.y; acc[3][2] += a.w * b.z; acc[3][3] += a.w * b.w;
        }
        __syncthreads();
    }
#pragma unroll
    for (int i = 0; i < 4; i++) {
        int r = row0 + (ty << 2) + i;
        if (r >= M) continue;
#pragma unroll
        for (int j = 0; j < 4; j++) {
            int c = col0 + (tx << 2) + j;
            float v = acc[i][j];
            if (bias) v += bias[c];
            if (res)  v += res[(size_t)r * N + c];
            C[(size_t)r * N + c] = v;
        }
    }
}

// ---------------- generic C = A@B^T + bias (used for patch embed) --------------
__global__ void gemm_abt_bias(const float* __restrict__ A, int lda,
                              const float* __restrict__ B, int ldb,
                              const float* __restrict__ bias, float* __restrict__ C,
                              int M, int N, int K) {
    __shared__ float As[16][64];
    __shared__ float Bs[16][64];
    const int tid = threadIdx.x;
    const int tx = tid & 15, ty = tid >> 4;
    const int row0 = blockIdx.y * 64, col0 = blockIdx.x * 64;
    const int lr = tid >> 2, lc = (tid & 3) << 2;
    float acc[4][4] = {};
    for (int k0 = 0; k0 < K; k0 += 16) {
        float4 av = make_float4(0.f, 0.f, 0.f, 0.f);
        if (row0 + lr < M) av = *(const float4*)(A + (size_t)(row0 + lr) * lda + k0 + lc);
        As[lc + 0][lr] = av.x; As[lc + 1][lr] = av.y;
        As[lc + 2][lr] = av.z; As[lc + 3][lr] = av.w;
        float4 bv = make_float4(0.f, 0.f, 0.f, 0.f);
        if (col0 + lr < N) bv = *(const float4*)(B + (size_t)(col0 + lr) * ldb + k0 + lc);
        Bs[lc + 0][lr] = bv.x; Bs[lc + 1][lr] = bv.y;
        Bs[lc + 2][lr] = bv.z; Bs[lc + 3][lr] = bv.w;
        __syncthreads();
#pragma unroll
        for (int kk = 0; kk < 16; kk++) {
            float4 a = *(const float4*)&As[kk][ty << 2];
            float4 b = *(const float4*)&Bs[kk][tx << 2];
            acc[0][0] += a.x * b.x; acc[0][1] += a.x * b.y; acc[0][2] += a.x * b.z; acc[0][3] += a.x * b.w;
            acc[1][0] += a.y * b.x; acc[1][1] += a.y * b.y; acc[1][2] += a.y * b.z; acc[1][3] += a.y * b.w;
            acc[2][0] += a.z * b.x; acc[2][1] += a.z * b.y; acc[2][2] += a.z * b.z; acc[2][3] += a.z * b.w;
            acc[3][0] += a.w * b.x; acc[3][1] += a.w * b.y; acc[3][2] += a.w * b.z; acc[3][3] += a.w * b.w;
        }
        __syncthreads();
    }
#pragma unroll
    for (int i = 0; i < 4; i++) {
        int r = row0 + (ty << 2) + i;
        if (r >= M) continue;
#pragma unroll
        for (int j = 0; j < 4; j++) {
            int c = col0 + (tx << 2) + j;
            if (c >= N) continue;
            C[(size_t)r * N + c] = acc[i][j] + (bias ? bias[c] : 0.f);
        }
    }
}

// ---------------- attention: scores = Q @ K^T per (head, [frame]) --------------
// batch z: h = z/nseg, t = z%nseg ; Q row i at qkv[(t*seg+i)*2304 + h*64], K offset +768
__global__ void qk_kernel(const float* __restrict__ qkv, float* __restrict__ scores,
                          int seg, int nseg) {
    __shared__ float Qs[16][64];
    __shared__ float Ks[16][64];
    const int z = blockIdx.z;
    const int h = z / nseg, t = z - h * nseg;
    const float* Qb = qkv + (size_t)t * seg * QKVW + h * DHEAD;
    const float* Kb = Qb + 768;
    const int tid = threadIdx.x;
    const int tx = tid & 15, ty = tid >> 4;
    const int qrow0 = blockIdx.y * 64, krow0 = blockIdx.x * 64;
    const int lr = tid >> 2, lc = (tid & 3) << 2;
    float acc[4][4] = {};
#pragma unroll
    for (int k0 = 0; k0 < 64; k0 += 16) {
        float4 qv = make_float4(0.f, 0.f, 0.f, 0.f);
        if (qrow0 + lr < seg) qv = *(const float4*)(Qb + (size_t)(qrow0 + lr) * QKVW + k0 + lc);
        Qs[lc + 0][lr] = qv.x; Qs[lc + 1][lr] = qv.y;
        Qs[lc + 2][lr] = qv.z; Qs[lc + 3][lr] = qv.w;
        float4 kv = make_float4(0.f, 0.f, 0.f, 0.f);
        if (krow0 + lr < seg) kv = *(const float4*)(Kb + (size_t)(krow0 + lr) * QKVW + k0 + lc);
        Ks[lc + 0][lr] = kv.x; Ks[lc + 1][lr] = kv.y;
        Ks[lc + 2][lr] = kv.z; Ks[lc + 3][lr] = kv.w;
        __syncthreads();
#pragma unroll
        for (int kk = 0; kk < 16; kk++) {
            float4 a = *(const float4*)&Qs[kk][ty << 2];
            float4 b = *(const float4*)&Ks[kk][tx << 2];
            acc[0][0] += a.x * b.x; acc[0][1] += a.x * b.y; acc[0][2] += a.x * b.z; acc[0][3] += a.x * b.w;
            acc[1][0] += a.y * b.x; acc[1][1] += a.y * b.y; acc[1][2] += a.y * b.z; acc[1][3] += a.y * b.w;
            acc[2][0] += a.z * b.x; acc[2][1] += a.z * b.y; acc[2][2] += a.z * b.z; acc[2][3] += a.z * b.w;
            acc[3][0] += a.w * b.x; acc[3][1] += a.w * b.y; acc[3][2] += a.w * b.z; acc[3][3] += a.w * b.w;
        }
        __syncthreads();
    }
    float* Sb = scores + (size_t)z * seg * seg;
#pragma unroll
    for (int i = 0; i < 4; i++) {
        int r = qrow0 + (ty << 2) + i;
        if (r >= seg) continue;
#pragma unroll
        for (int j = 0; j < 4; j++) {
            int c = krow0 + (tx << 2) + j;
            if (c >= seg) continue;
            Sb[(size_t)r * seg + c] = acc[i][j];
        }
    }
}

// ---------------- row softmax with pre-scale (softmax(x*scale)) ----------------
__global__ void softmax_kernel(float* __restrict__ scores, int seg) {
    float* row = scores + (size_t)blockIdx.x * seg;
    const int tid = threadIdx.x;
    __shared__ float sh[32];
    float m = -1e30f;
    for (int i = tid; i < seg; i += 256) m = fmaxf(m, row[i]);
#pragma unroll
    for (int o = 16; o; o >>= 1) m = fmaxf(m, __shfl_xor_sync(0xffffffffu, m, o));
    if ((tid & 31) == 0) sh[tid >> 5] = m;
    __syncthreads();
    if (tid < 32) {
        float v = (tid < 8) ? sh[tid] : -1e30f;
#pragma unroll
        for (int o = 4; o; o >>= 1) v = fmaxf(v, __shfl_xor_sync(0xffffffffu, v, o));
        if (tid == 0) sh[0] = v;
    }
    __syncthreads();
    m = sh[0];
    __syncthreads();
    float s = 0.f;
    for (int i = tid; i < seg; i += 256) {
        float e = __expf((row[i] - m) * SCALE_);
        row[i] = e;
        s += e;
    }
#pragma unroll
    for (int o = 16; o; o >>= 1) s += __shfl_xor_sync(0xffffffffu, s, o);
    if ((tid & 31) == 0) sh[tid >> 5] = s;
    __syncthreads();
    if (tid < 32) {
        float v = (tid < 8) ? sh[tid] : 0.f;
#pragma unroll
        for (int o = 4; o; o >>= 1) v += __shfl_xor_sync(0xffffffffu, v, o);
        if (tid == 0) sh[0] = v;
    }
    __syncthreads();
    float inv = 1.0f / sh[0];
    for (int i = tid; i < seg; i += 256) row[i] *= inv;
}

// ---------------- V mean over tokens within a frame (divided temporal path) ----
__global__ void vmean_kernel(const float* __restrict__ qkv, float* __restrict__ vmean) {
    int z = blockIdx.x;          // z = h*8 + t
    int h = z >> 3, t = z & 7;
    int d = threadIdx.x;         // 0..63
    const float* base = qkv + (size_t)t * NSEQ * QKVW + 1536 + h * DHEAD + d;
    float s = 0.f;
    for (int n = 0; n < NSEQ; n++) s += base[(size_t)n * QKVW];
    vmean[z * DHEAD + d] = s * (1.0f / (float)NSEQ);
}

// ---------------- O = P @ V (+ optional vmean broadcast), writes [tok, h*64+c] -
__global__ void av_kernel(const float* __restrict__ scores, const float* __restrict__ qkv,
                          float* __restrict__ O, int seg, int nseg,
                          const float* __restrict__ vmean) {
    __shared__ float Ps[16][64];
    __shared__ float Vs[16][64];
    const int z = blockIdx.y;
    const int h = z / nseg, t = z - h * nseg;
    const float* P = scores + (size_t)z * seg * seg;
    const float* Vb = qkv + (size_t)t * seg * QKVW + 1536 + h * DHEAD;
    const int tid = threadIdx.x;
    const int tx = tid & 15, ty = tid >> 4;
    const int row0 = blockIdx.x * 64;
    const int lr = tid >> 2, lc = (tid & 3) << 2;   // P tile: row, kcol
    const int br = tid >> 4, bc = (tid & 15) << 2;  // V tile: krow, col
    float acc[4][4] = {};
    const int Kpad = (seg + 15) & ~15;
    for (int k0 = 0; k0 < Kpad; k0 += 16) {
        // P tile: scalar loads (seg may be 197 -> unaligned/ragged)
        int prow = row0 + lr;
#pragma unroll
        for (int q = 0; q < 4; q++) {
            int kc = k0 + lc + q;
            float v = 0.f;
            if (prow < seg && kc < seg) v = P[(size_t)prow * seg + kc];
            Ps[lc + q][lr] = v;
        }
        float4 vv = make_float4(0.f, 0.f, 0.f, 0.f);
        if (k0 + br < seg) vv = *(const float4*)(Vb + (size_t)(k0 + br) * QKVW + bc);
        *(float4*)&Vs[br][bc] = vv;
        __syncthreads();
#pragma unroll
        for (int kk = 0; kk < 16; kk++) {
            float4 a = *(const float4*)&Ps[kk][ty << 2];
            float4 b = *(const float4*)&Vs[kk][tx << 2];
            acc[0][0] += a.x * b.x; acc[0][1] += a.x * b.y; acc[0][2] += a.x * b.z; acc[0][3] += a.x * b.w;
            acc[1][0] += a.y * b.x; acc[1][1] += a.y * b.y; acc[1][2] += a.y * b.z; acc[1][3] += a.y * b.w;
            acc[2][0] += a.z * b.x; acc[2][1] += a.z * b.y; acc[2][2] += a.z * b.z; acc[2][3] += a.z * b.w;
            acc[3][0] += a.w * b.x; acc[3][1] += a.w * b.y; acc[3][2] += a.w * b.z; acc[3][3] += a.w * b.w;
        }
        __syncthreads();
    }
#pragma unroll
    for (int i = 0; i < 4; i++) {
        int r = row0 + (ty << 2) + i;
        if (r >= seg) continue;
        int tok = t * seg + r;
#pragma unroll
        for (int j = 0; j < 4; j++) {
            int c = (tx << 2) + j;   // 0..63
            float v = acc[i][j];
            if (vmean) v += vmean[z * DHEAD + c];
            O[(size_t)tok * DMODEL + h * DHEAD + c] = v;
        }
    }
}

// ---------------- LayerNorm over 768 (one block per row) -----------------------
__global__ void layernorm_kernel(const float* __restrict__ X, const float* __restrict__ g,
                                 const float* __restrict__ b, float* __restrict__ Y) {
    const int row = blockIdx.x;
    const float* x = X + (size_t)row * DMODEL;
    const int tid = threadIdx.x;
    __shared__ float sh[32];
    float v0 = x[tid], v1 = x[tid + 256], v2 = x[tid + 512];
    float s = v0 + v1 + v2;
#pragma unroll
    for (int o = 16; o; o >>= 1) s += __shfl_xor_sync(0xffffffffu, s, o);
    if ((tid & 31) == 0) sh[tid >> 5] = s;
    __syncthreads();
    if (tid < 32) {
        float v = (tid < 8) ? sh[tid] : 0.f;
#pragma unroll
        for (int o = 4; o; o >>= 1) v += __shfl_xor_sync(0xffffffffu, v, o);
        if (tid == 0) sh[0] = v;
    }
    __syncthreads();
    float mu = sh[0] * (1.0f / (float)DMODEL);
    __syncthreads();
    float d0 = v0 - mu, d1 = v1 - mu, d2 = v2 - mu;
    s = d0 * d0 + d1 * d1 + d2 * d2;
#pragma unroll
    for (int o = 16; o; o >>= 1) s += __shfl_xor_sync(0xffffffffu, s, o);
    if ((tid & 31) == 0) sh[tid >> 5] = s;
    __syncthreads();
    if (tid < 32) {
        float v = (tid < 8) ? sh[tid] : 0.f;
#pragma unroll
        for (int o = 4; o; o >>= 1) v += __shfl_xor_sync(0xffffffffu, v, o);
        if (tid == 0) sh[0] = v;
    }
    __syncthreads();
    float rstd = rsqrtf(sh[0] * (1.0f / (float)DMODEL) + 1e-5f);
    float* y = Y + (size_t)row * DMODEL;
    y[tid]       = d0 * rstd * g[tid]       + b[tid];
    y[tid + 256] = d1 * rstd * g[tid + 256] + b[tid + 256];
    y[tid + 512] = d2 * rstd * g[tid + 512] + b[tid + 512];
}

// ---------------- exact GELU ----------------------------------------------------
__global__ void gelu_kernel(float* __restrict__ x, int n) {
    int i = blockIdx.x * 256 + threadIdx.x;
    if (i < n) {
        float v = x[i];
        x[i] = 0.5f * v * (1.0f + erff(v * 0.70710678118654752f));
    }
}

// ---------------- launch ---------------------------------------------------------
extern "C" void kernel_launch(void* const* d_in, const int* in_sizes, int n_in,
                              void* d_out, int out_size) {
    (void)in_sizes; (void)n_in; (void)out_size;
    float* ws = nullptr;
    cudaGetSymbolAddress((void**)&ws, g_ws);

    float* patch  = ws + WS_PATCH;
    float* emb    = ws + WS_EMB;
    float* h      = ws + WS_H;
    float* a      = ws + WS_A;
    float* qkv    = ws + WS_QKV;
    float* scores = ws + WS_SCORES;
    float* o      = ws + WS_O;
    float* mlp    = ws + WS_MLP;
    float* vmean  = ws + WS_VMEAN;

    const float* x      = (const float*)d_in[0];
    const float* Wp     = (const float*)d_in[1];
    const float* bp     = (const float*)d_in[2];
    const float* cls    = (const float*)d_in[3];
    const float* pos    = (const float*)d_in[4];
    const float* ln1_g  = (const float*)d_in[5];
    const float* ln1_b  = (const float*)d_in[6];
    const float* qkv_w  = (const float*)d_in[7];
    const float* qkv_b  = (const float*)d_in[8];
    const float* proj_w = (const float*)d_in[9];
    const float* proj_b = (const float*)d_in[10];
    const float* ln2_g  = (const float*)d_in[11];
    const float* ln2_b  = (const float*)d_in[12];
    const float* fc1_w  = (const float*)d_in[13];
    const float* fc1_b  = (const float*)d_in[14];
    const float* fc2_w  = (const float*)d_in[15];
    const float* fc2_b  = (const float*)d_in[16];
    const float* lnf_g  = (const float*)d_in[17];
    const float* lnf_b  = (const float*)d_in[18];

    // patch embed
    gather_patches<<<(1568 * 768 + 255) / 256, 256>>>(x, patch);
    gemm_abt_bias<<<dim3(768 / 64, (1568 + 63) / 64), 256>>>(patch, 768, Wp, 768, bp, emb,
                                                             1568, 768, 768);
    assemble_h<<<(NTOK * DMODEL + 255) / 256, 256>>>(emb, cls, pos, h);

    for (int i = 0; i < 12; i++) {
        // ---- attention ----
        layernorm_kernel<<<NTOK, 256>>>(h, ln1_g + i * DMODEL, ln1_b + i * DMODEL, a);
        sgemm_bias<<<dim3(QKVW / 64, (NTOK + 63) / 64), 256>>>(
            a, qkv_w + (size_t)i * DMODEL * QKVW, qkv_b + i * QKVW, nullptr, qkv,
            NTOK, QKVW, DMODEL);

        if ((i & 1) == 0) {
            // divided space-time: spatial attn per frame + V-mean broadcast
            vmean_kernel<<<NHEAD * T_FR, DHEAD>>>(qkv, vmean);
            qk_kernel<<<dim3(4, 4, NHEAD * T_FR), 256>>>(qkv, scores, NSEQ, T_FR);
            softmax_kernel<<<NHEAD * T_FR * NSEQ, 256>>>(scores, NSEQ);
            av_kernel<<<dim3(4, NHEAD * T_FR), 256>>>(scores, qkv, o, NSEQ, T_FR, vmean);
        } else {
            // joint space-time
            qk_kernel<<<dim3(25, 25, NHEAD), 256>>>(qkv, scores, NTOK, 1);
            softmax_kernel<<<NHEAD * NTOK, 256>>>(scores, NTOK);
            av_kernel<<<dim3(25, NHEAD), 256>>>(scores, qkv, o, NTOK, 1, nullptr);
        }
        // h += proj(o)   (in-place residual: each thread reads/writes its own elem)
        sgemm_bias<<<dim3(DMODEL / 64, (NTOK + 63) / 64), 256>>>(
            o, proj_w + (size_t)i * DMODEL * DMODEL, proj_b + i * DMODEL, h, h,
            NTOK, DMODEL, DMODEL);

        // ---- mlp ----
        layernorm_kernel<<<NTOK, 256>>>(h, ln2_g + i * DMODEL, ln2_b + i * DMODEL, a);
        sgemm_bias<<<dim3(DMLP / 64, (NTOK + 63) / 64), 256>>>(
            a, fc1_w + (size_t)i * DMODEL * DMLP, fc1_b + i * DMLP, nullptr, mlp,
            NTOK, DMLP, DMODEL);
        gelu_kernel<<<(NTOK * DMLP + 255) / 256, 256>>>(mlp, NTOK * DMLP);
        sgemm_bias<<<dim3(DMODEL / 64, (NTOK + 63) / 64), 256>>>(
            mlp, fc2_w + (size_t)i * DMLP * DMODEL, fc2_b + i * DMODEL, h, h,
            NTOK, DMODEL, DMLP);
    }

    layernorm_kernel<<<NTOK, 256>>>(h, lnf_g, lnf_b, (float*)d_out);
}